// round 3
// baseline (speedup 1.0000x reference)
#include <cuda_runtime.h>
#include <math.h>

#define TTOK 8192
#define DM   1024
#define DFF  4096
#define NE   8

#define BM 128
#define BN 64
#define BK 16

// ---------------- scratch (static device globals: allowed) ----------------
__device__ int   g_counts[NE];
__device__ int   g_pair[NE][TTOK];     // pair id = token*2 + slot
__device__ float g_wt[NE][TTOK];       // combine weight for that pair
__device__ float g_H[(size_t)2 * TTOK * DFF];  // 256 MB intermediate
__device__ float g_Y[(size_t)2 * TTOK * DM];   // 64 MB per-pair outputs

// ---------------- init: reset per-launch state ----------------
__global__ void k_init() {
    if (threadIdx.x < NE) g_counts[threadIdx.x] = 0;
}

// ---------------- router: one warp per token ----------------
__global__ void k_router(const float* __restrict__ x,
                         const float* __restrict__ gW,
                         const float* __restrict__ gb) {
    int t    = (blockIdx.x * blockDim.x + threadIdx.x) >> 5;
    int lane = threadIdx.x & 31;
    if (t >= TTOK) return;
    const float* xr = x + (size_t)t * DM;

    float acc[NE];
#pragma unroll
    for (int e = 0; e < NE; e++) acc[e] = 0.f;

    for (int i = lane; i < DM; i += 32) {
        float xv = xr[i];
#pragma unroll
        for (int e = 0; e < NE; e++) acc[e] += xv * gW[e * DM + i];
    }
#pragma unroll
    for (int e = 0; e < NE; e++) {
#pragma unroll
        for (int o = 16; o > 0; o >>= 1)
            acc[e] += __shfl_down_sync(0xffffffffu, acc[e], o);
    }
    if (lane == 0) {
        float best = -1e30f, sec = -1e30f;
        int b0 = 0, b1 = 0;
#pragma unroll
        for (int e = 0; e < NE; e++) {
            float l = acc[e] + gb[e];
            if (l > best)      { sec = best; b1 = b0; best = l; b0 = e; }
            else if (l > sec)  { sec = l; b1 = e; }
        }
        float ex = expf(sec - best);       // softmax over top-2
        float inv = 1.f / (1.f + ex);
        float w0 = inv, w1 = ex * inv;
        int i0 = atomicAdd(&g_counts[b0], 1);
        g_pair[b0][i0] = t * 2;     g_wt[b0][i0] = w0;
        int i1 = atomicAdd(&g_counts[b1], 1);
        g_pair[b1][i1] = t * 2 + 1; g_wt[b1][i1] = w1;
    }
}

// ---------------- grouped GEMM 1: H = silu(X Wg^T) * (X W1^T) ----------------
// grid: (DFF/BN, TTOK/BM, NE). block 256 threads, 8x4 thread tile, dual accum.
__global__ __launch_bounds__(256)
void k_ffn1(const float* __restrict__ x,
            const float* __restrict__ Wg,
            const float* __restrict__ W1) {
    int e   = blockIdx.z;
    int cnt = g_counts[e];
    int m0  = blockIdx.y * BM;
    if (m0 >= cnt) return;
    int n0  = blockIdx.x * BN;

    __shared__ float sA[BK][BM + 4];
    __shared__ float sG[BK][BN + 4];
    __shared__ float sV[BK][BN + 4];
    __shared__ int   sPair[BM];

    int tid = threadIdx.x;
    if (tid < BM) {
        int r  = m0 + tid;
        int rr = r < cnt ? r : cnt - 1;
        sPair[tid] = g_pair[e][rr];
    }
    __syncthreads();

    const float* Bg = Wg + (size_t)e * DFF * DM + (size_t)n0 * DM;
    const float* Bv = W1 + (size_t)e * DFF * DM + (size_t)n0 * DM;

    int tcol = (tid & 15) * 4;   // 0..60
    int trow = (tid >> 4) * 8;   // 0..120

    float accG[8][4], accV[8][4];
#pragma unroll
    for (int i = 0; i < 8; i++)
#pragma unroll
        for (int j = 0; j < 4; j++) { accG[i][j] = 0.f; accV[i][j] = 0.f; }

    // precompute this thread's A-load rows (2 float4s per chunk)
    int am0 = tid >> 2;            int ak0 = (tid & 3) * 4;
    int am1 = (tid + 256) >> 2;    int ak1 = ak0;  // same (f&3) pattern
    const float* arow0 = x + (size_t)(sPair[am0] >> 1) * DM;
    const float* arow1 = x + (size_t)(sPair[am1] >> 1) * DM;
    int bn = tid >> 2;             int bk = (tid & 3) * 4;
    const float* bgrow = Bg + (size_t)bn * DM;
    const float* bvrow = Bv + (size_t)bn * DM;

    for (int k0 = 0; k0 < DM; k0 += BK) {
        float4 a0 = *(const float4*)(arow0 + k0 + ak0);
        float4 a1 = *(const float4*)(arow1 + k0 + ak1);
        float4 bg = *(const float4*)(bgrow + k0 + bk);
        float4 bv = *(const float4*)(bvrow + k0 + bk);
        sA[ak0 + 0][am0] = a0.x; sA[ak0 + 1][am0] = a0.y;
        sA[ak0 + 2][am0] = a0.z; sA[ak0 + 3][am0] = a0.w;
        sA[ak1 + 0][am1] = a1.x; sA[ak1 + 1][am1] = a1.y;
        sA[ak1 + 2][am1] = a1.z; sA[ak1 + 3][am1] = a1.w;
        sG[bk + 0][bn] = bg.x; sG[bk + 1][bn] = bg.y;
        sG[bk + 2][bn] = bg.z; sG[bk + 3][bn] = bg.w;
        sV[bk + 0][bn] = bv.x; sV[bk + 1][bn] = bv.y;
        sV[bk + 2][bn] = bv.z; sV[bk + 3][bn] = bv.w;
        __syncthreads();

#pragma unroll
        for (int kk = 0; kk < BK; kk++) {
            float a[8];
            *(float4*)&a[0] = *(const float4*)&sA[kk][trow];
            *(float4*)&a[4] = *(const float4*)&sA[kk][trow + 4];
            float bgf[4]; *(float4*)bgf = *(const float4*)&sG[kk][tcol];
            float bvf[4]; *(float4*)bvf = *(const float4*)&sV[kk][tcol];
#pragma unroll
            for (int i = 0; i < 8; i++)
#pragma unroll
                for (int j = 0; j < 4; j++) {
                    accG[i][j] += a[i] * bgf[j];
                    accV[i][j] += a[i] * bvf[j];
                }
        }
        __syncthreads();
    }

    // epilogue: H = silu(G) * V
#pragma unroll
    for (int i = 0; i < 8; i++) {
        int r = m0 + trow + i;
        if (r < cnt) {
            int pair = sPair[trow + i];
            float4 hv;
            float g0 = accG[i][0]; hv.x = (g0 / (1.f + expf(-g0))) * accV[i][0];
            float g1 = accG[i][1]; hv.y = (g1 / (1.f + expf(-g1))) * accV[i][1];
            float g2 = accG[i][2]; hv.z = (g2 / (1.f + expf(-g2))) * accV[i][2];
            float g3 = accG[i][3]; hv.w = (g3 / (1.f + expf(-g3))) * accV[i][3];
            *(float4*)(g_H + (size_t)pair * DFF + n0 + tcol) = hv;
        }
    }
}

// ---------------- grouped GEMM 2: Y = (H @ W2^T) * w ----------------
// grid: (DM/BN, TTOK/BM, NE)
__global__ __launch_bounds__(256)
void k_ffn2(const float* __restrict__ W2) {
    int e   = blockIdx.z;
    int cnt = g_counts[e];
    int m0  = blockIdx.y * BM;
    if (m0 >= cnt) return;
    int n0  = blockIdx.x * BN;

    __shared__ float sA[BK][BM + 4];
    __shared__ float sB[BK][BN + 4];
    __shared__ int   sPair[BM];

    int tid = threadIdx.x;
    if (tid < BM) {
        int r  = m0 + tid;
        int rr = r < cnt ? r : cnt - 1;
        sPair[tid] = g_pair[e][rr];
    }
    __syncthreads();

    const float* B = W2 + (size_t)e * DM * DFF + (size_t)n0 * DFF;

    int tcol = (tid & 15) * 4;
    int trow = (tid >> 4) * 8;

    float acc[8][4];
#pragma unroll
    for (int i = 0; i < 8; i++)
#pragma unroll
        for (int j = 0; j < 4; j++) acc[i][j] = 0.f;

    int am0 = tid >> 2;          int ak0 = (tid & 3) * 4;
    int am1 = (tid + 256) >> 2;
    const float* arow0 = g_H + (size_t)sPair[am0] * DFF;
    const float* arow1 = g_H + (size_t)sPair[am1] * DFF;
    int bn = tid >> 2;           int bk = (tid & 3) * 4;
    const float* brow = B + (size_t)bn * DFF;

    for (int k0 = 0; k0 < DFF; k0 += BK) {
        float4 a0 = *(const float4*)(arow0 + k0 + ak0);
        float4 a1 = *(const float4*)(arow1 + k0 + ak0);
        float4 b4 = *(const float4*)(brow + k0 + bk);
        sA[ak0 + 0][am0] = a0.x; sA[ak0 + 1][am0] = a0.y;
        sA[ak0 + 2][am0] = a0.z; sA[ak0 + 3][am0] = a0.w;
        sA[ak0 + 0][am1] = a1.x; sA[ak0 + 1][am1] = a1.y;
        sA[ak0 + 2][am1] = a1.z; sA[ak0 + 3][am1] = a1.w;
        sB[bk + 0][bn] = b4.x; sB[bk + 1][bn] = b4.y;
        sB[bk + 2][bn] = b4.z; sB[bk + 3][bn] = b4.w;
        __syncthreads();

#pragma unroll
        for (int kk = 0; kk < BK; kk++) {
            float a[8];
            *(float4*)&a[0] = *(const float4*)&sA[kk][trow];
            *(float4*)&a[4] = *(const float4*)&sA[kk][trow + 4];
            float bf[4]; *(float4*)bf = *(const float4*)&sB[kk][tcol];
#pragma unroll
            for (int i = 0; i < 8; i++)
#pragma unroll
                for (int j = 0; j < 4; j++) acc[i][j] += a[i] * bf[j];
        }
        __syncthreads();
    }

#pragma unroll
    for (int i = 0; i < 8; i++) {
        int r = m0 + trow + i;
        if (r < cnt) {
            int   pair = sPair[trow + i];
            float w    = g_wt[e][r];
            float4 yv;
            yv.x = acc[i][0] * w; yv.y = acc[i][1] * w;
            yv.z = acc[i][2] * w; yv.w = acc[i][3] * w;
            *(float4*)(g_Y + (size_t)pair * DM + n0 + tcol) = yv;
        }
    }
}

// ---------------- combine: out[t] = Y[2t] + Y[2t+1] ----------------
__global__ void k_combine(float* __restrict__ out) {
    size_t i = (size_t)blockIdx.x * blockDim.x + threadIdx.x;  // over T*DM/4
    const float4* y = (const float4*)g_Y;
    int t = (int)(i >> 8);          // DM/4 = 256 vec elems per row
    int j = (int)(i & 255);
    float4 a = y[(size_t)(2 * t) * 256 + j];
    float4 b = y[(size_t)(2 * t + 1) * 256 + j];
    float4 o;
    o.x = a.x + b.x; o.y = a.y + b.y; o.z = a.z + b.z; o.w = a.w + b.w;
    ((float4*)out)[i] = o;
}

// ---------------- launch ----------------
extern "C" void kernel_launch(void* const* d_in, const int* in_sizes, int n_in,
                              void* d_out, int out_size) {
    const float* x  = (const float*)d_in[0];
    const float* gW = (const float*)d_in[1];
    const float* gb = (const float*)d_in[2];
    const float* Wg = (const float*)d_in[3];
    const float* W1 = (const float*)d_in[4];
    const float* W2 = (const float*)d_in[5];
    float* out = (float*)d_out;

    k_init<<<1, 32>>>();
    k_router<<<TTOK / 8, 256>>>(x, gW, gb);   // 8 warps/block -> 8 tokens/block

    dim3 g1(DFF / BN, TTOK / BM, NE);
    k_ffn1<<<g1, 256>>>(x, Wg, W1);

    dim3 g2(DM / BN, TTOK / BM, NE);
    k_ffn2<<<g2, 256>>>(W2);

    k_combine<<<(TTOK * (DM / 4)) / 256, 256>>>(out);
}